// round 15
// baseline (speedup 1.0000x reference)
#include <cuda_runtime.h>
#include <math.h>
#include <stdint.h>

#define NN      2304                    // 48*48
#define BB      2
#define CF      32
#define TILE    64
#define NT      (NN / TILE)             // 36
#define TPAIRS  (NT * (NT + 1) / 2)     // 666
#define NWORK   (BB * TPAIRS)           // 1332 tile-pairs
#define NLAUNCH 592                     // 148 SMs x 4 resident, single wave
#define MAXREP  3                       // bid<148: 3 reps, else 2 (148*3+444*2=1332)
#define PCH     3
#define KP      2.8853900817779268f     // 4 / ln(4)
#define CEXP    -5.770780163555851f     // -4 * log2(e)
#define SQ2     1.4142135623730951f
#define PITCH   36                      // u32 pitch, conflict-free frag loads

typedef unsigned long long u64;
typedef unsigned int u32;

// ---- scratch (no allocations allowed) ----
__device__ float4   g_st4[BB * NN];     // (mu, var, 0.25/var, -mu)
__device__ float4   g_pa4[BB * NN];     // (sqrt2*pE1..3, q1^2)
__device__ float2   g_pb2[BB * NN];     // (q2^2, q3^2)
__device__ __align__(16) u32 g_ftf[BB * NN * CF];   // normalized tf32, node-major
__device__ float    g_partial[NLAUNCH];
__device__ int      g_count = 0;

// ---- packed f32x2 helpers (sm_103a) ----
#define FMA2(d, a, b, c) asm("fma.rn.f32x2 %0, %1, %2, %3;" \
    : "=l"(d) : "l"(a), "l"(b), "l"(c))
#define MUL2(d, a, b) asm("mul.rn.f32x2 %0, %1, %2;" : "=l"(d) : "l"(a), "l"(b))
#define ADD2(d, a, b) asm("add.rn.f32x2 %0, %1, %2;" : "=l"(d) : "l"(a), "l"(b))
#define PACK2(d, x) asm("mov.b64 %0, {%1, %1};" : "=l"(d) : "f"(x))
#define PACKW(d, lo, hi) asm("mov.b64 %0, {%1, %2};" : "=l"(d) : "f"(lo), "f"(hi))
#define UNPACK2(lo, hi, v) asm("mov.b64 {%0, %1}, %2;" : "=f"(lo), "=f"(hi) : "l"(v))
#define CVT_TF32(d, x) asm("cvt.rna.tf32.f32 %0, %1;" : "=r"(d) : "f"(x))

__device__ __forceinline__ float ex2f(float x) {
    float r; asm("ex2.approx.f32 %0, %1;" : "=f"(r) : "f"(x)); return r;
}
__device__ __forceinline__ float rcpf(float x) {
    float r; asm("rcp.approx.f32 %0, %1;" : "=f"(r) : "f"(x)); return r;
}
__device__ __forceinline__ u32 smem_u32(const void* p) {
    u32 a; asm("{ .reg .u64 t; cvta.to.shared.u64 t, %1; cvt.u32.u64 %0, t; }"
               : "=r"(a) : "l"(p));
    return a;
}
#define CP_ASYNC16(daddr, gp) asm volatile( \
    "cp.async.cg.shared.global [%0], [%1], 16;" :: "r"(daddr), "l"(gp) : "memory")
#define CP_COMMIT() asm volatile("cp.async.commit_group;" ::: "memory")
#define CP_WAIT(n)  asm volatile("cp.async.wait_group %0;" :: "n"(n) : "memory")

// m16n8k8 tf32 mma, D += A*B  (row.col)
#define MMA_TF32(d, a0, a1, a2, a3, b0, b1) asm volatile( \
    "mma.sync.aligned.m16n8k8.row.col.f32.tf32.tf32.f32 " \
    "{%0,%1,%2,%3}, {%4,%5,%6,%7}, {%8,%9}, {%0,%1,%2,%3};" \
    : "+f"((d)[0]), "+f"((d)[1]), "+f"((d)[2]), "+f"((d)[3]) \
    : "r"(a0), "r"(a1), "r"(a2), "r"(a3), "r"(b0), "r"(b1))

// ============================================================
// Kernel A: stats + softmax + normalized tf32 feature rows
// ============================================================
__global__ void precompute_kernel(const float* __restrict__ f,
                                  const float* __restrict__ p) {
    int idx = blockIdx.x * 64 + threadIdx.x;
    if (idx >= BB * NN) return;
    int b = idx / NN;
    int n = idx - b * NN;

    const float* fb = f + (size_t)b * CF * NN + n;
    float v[CF];
    float s = 0.0f, ss = 0.0f;
#pragma unroll
    for (int c = 0; c < CF; c++) {
        v[c] = fb[c * NN];
        s += v[c];
        ss = fmaf(v[c], v[c], ss);
    }
    float mu  = s * (1.0f / CF);
    float var = (ss - s * mu) * (1.0f / (CF - 1));
    g_st4[idx] = make_float4(mu, var, 0.25f / var, -mu);

    float inorm = rsqrtf(ss);
    u32* frow = &g_ftf[idx * CF];
#pragma unroll
    for (int c4 = 0; c4 < CF / 4; c4++) {
        uint4 o;
        CVT_TF32(o.x, v[4 * c4 + 0] * inorm);
        CVT_TF32(o.y, v[4 * c4 + 1] * inorm);
        CVT_TF32(o.z, v[4 * c4 + 2] * inorm);
        CVT_TF32(o.w, v[4 * c4 + 3] * inorm);
        *(uint4*)&frow[4 * c4] = o;
    }

    const float* pp = p + (size_t)b * 4 * NN + n;
    float e0 = __expf(pp[0]);
    float e1 = __expf(pp[NN]);
    float e2 = __expf(pp[2 * NN]);
    float e3 = __expf(pp[3 * NN]);
    float inv = __fdividef(1.0f, e0 + e1 + e2 + e3);
    float q1 = e1 * inv, q2 = e2 * inv, q3 = e3 * inv;
    float E1 = fmaf(KP * q1, __logf(q1), 1.0f);
    float E2 = fmaf(KP * q2, __logf(q2), 1.0f);
    float E3 = fmaf(KP * q3, __logf(q3), 1.0f);
    g_pa4[idx] = make_float4(SQ2 * q1 * E1, SQ2 * q2 * E2, SQ2 * q3 * E3, q1 * q1);
    g_pb2[idx] = make_float2(q2 * q2, q3 * q3);
}

// ============================================================
// Kernel B: 592 blocks x 256 thr (occ 4, single wave, 2-3 reps)
//   cp.async double-buffered tf32 tiles, mma.sync gram,
//   record-packed f32x2 epilogue (R10 structure, occ-4 config)
// ============================================================
__global__ void __launch_bounds__(256, 4) pair_kernel(float* __restrict__ out) {
    __shared__ __align__(16) u32 ftile[2][2][TILE][PITCH];  // [buf][side][row][k]
    __shared__ __align__(16) u64 id_q[TILE][10];            // i recs (dup pairs)
    __shared__ __align__(16) u64 js_q[TILE / 2][10];        // j recs (j, j+1)
    __shared__ float red_s[8];
    __shared__ int   is_last;

    int bid  = blockIdx.x;
    int t    = threadIdx.x;
    int lane = t & 31, warp = t >> 5;
    int g    = lane >> 2, tig = lane & 3;   // mma fragment coords
    int ar0  = (warp & 3) * 16 + g;         // first i row of this thread
    int jb   = (warp >> 2) * 32;            // warp's j block

    int nrep = (bid < 148) ? 3 : 2;

    // decode rep -> (b, i0, j0, offdiag)
    int I0[MAXREP], J0[MAXREP], BN[MAXREP], OD[MAXREP];
#pragma unroll
    for (int rep = 0; rep < MAXREP; rep++) {
        int tp = bid + rep * NLAUNCH;
        if (tp >= NWORK) tp = bid;          // dummy (never executed)
        int b  = tp / TPAIRS;
        int r  = tp - b * TPAIRS;
        int ti = 0;
        while (r >= NT - ti) { r -= NT - ti; ti++; }
        int tj = ti + r;
        BN[rep] = b * NN;
        I0[rep] = ti * TILE;
        J0[rep] = tj * TILE;
        OD[rep] = (ti != tj);
    }

    u64 C13, CM23, CHALF, CEXP2;
    PACK2(C13,   (1.0f / 3.0f));
    PACK2(CM23, (-2.0f / 3.0f));
    PACK2(CHALF, 0.5f);
    PACK2(CEXP2, CEXP);

    // prologue: stage f tiles for rep 0 into buf 0
#pragma unroll
    for (int k = 0; k < 4; k++) {
        int ch   = t + 256 * k;             // 0..1023 16B chunks
        int sg   = ch & 7;
        int rw   = (ch >> 3) & 63;
        int sd   = ch >> 9;
        int base = sd ? J0[0] : I0[0];
        const u32* gp = &g_ftf[(BN[0] + base + rw) * CF + sg * 4];
        CP_ASYNC16(smem_u32(&ftile[0][sd][rw][sg * 4]), gp);
    }
    CP_COMMIT();

    float part = 0.0f;

#pragma unroll 1
    for (int rep = 0; rep < nrep; rep++) {
        int cur = rep & 1;
        int bNN = BN[rep], i0 = I0[rep], j0 = J0[rep];

        __syncthreads();                    // prev compute done; stat bufs free

        // ---- stage stat records ----
        if (t < TILE) {
            int e = t;
            float4 si = g_st4[bNN + i0 + e];
            float4 pi = g_pa4[bNN + i0 + e];
            float2 qi = g_pb2[bNN + i0 + e];
            float rec[9] = {si.x, si.y, si.z, pi.x, pi.y, pi.z, pi.w, qi.x, qi.y};
            u64* dst = id_q[e];
#pragma unroll
            for (int a = 0; a < 9; a++) {
                u64 dv; PACK2(dv, rec[a]);
                dst[a] = dv;
            }
        } else if (t < 2 * TILE) {
            int e = t - TILE;
            float4 sj = g_st4[bNN + j0 + e];
            float4 pj = g_pa4[bNN + j0 + e];
            float2 qj = g_pb2[bNN + j0 + e];
            float rec[9] = {sj.w, sj.y, sj.z, pj.x, pj.y, pj.z, pj.w, qj.x, qj.y};
            float* dst = (float*)js_q[e >> 1] + (e & 1);
#pragma unroll
            for (int a = 0; a < 9; a++) dst[2 * a] = rec[a];
        }

        // ---- stage f tiles for rep+1 into the other buffer ----
        if (rep + 1 < nrep) {
#pragma unroll
            for (int k = 0; k < 4; k++) {
                int ch   = t + 256 * k;
                int sg   = ch & 7;
                int rw   = (ch >> 3) & 63;
                int sd   = ch >> 9;
                int base = sd ? J0[rep + 1] : I0[rep + 1];
                const u32* gp = &g_ftf[(BN[rep + 1] + base + rw) * CF + sg * 4];
                CP_ASYNC16(smem_u32(&ftile[1 - cur][sd][rw][sg * 4]), gp);
            }
            CP_COMMIT();
            CP_WAIT(1);                     // cur's group done
        } else {
            CP_WAIT(0);
        }
        __syncthreads();                    // staging visible

        // ---- gram via mma.sync: warp tile 16i x 32j, K=32 ----
        const u32 (*as32)[PITCH] = ftile[cur][0];
        const u32 (*bs32)[PITCH] = ftile[cur][1];
        float acc[4][4];
#pragma unroll
        for (int n = 0; n < 4; n++)
#pragma unroll
            for (int c = 0; c < 4; c++) acc[n][c] = 0.0f;

#pragma unroll
        for (int kk = 0; kk < 4; kk++) {
            int kb = 8 * kk + tig;
            u32 a0 = as32[ar0][kb];
            u32 a1 = as32[ar0 + 8][kb];
            u32 a2 = as32[ar0][kb + 4];
            u32 a3 = as32[ar0 + 8][kb + 4];
#pragma unroll
            for (int n = 0; n < 4; n++) {
                int bc = jb + 8 * n + g;
                u32 b0 = bs32[bc][kb];
                u32 b1 = bs32[bc][kb + 4];
                MMA_TF32(acc[n], a0, a1, a2, a3, b0, b1);
            }
        }

        // ---- epilogue: record loads, f32x2 math ----
        float tpart = 0.0f;
#pragma unroll
        for (int h = 0; h < 2; h++) {
            const u64* irec = id_q[ar0 + 8 * h];
            ulonglong2 iA = *(const ulonglong2*)&irec[0];   // mu, v
            ulonglong2 iB = *(const ulonglong2*)&irec[2];   // z, pE1
            ulonglong2 iC = *(const ulonglong2*)&irec[4];   // pE2, pE3
            ulonglong2 iD = *(const ulonglong2*)&irec[6];   // q1, q2
            u64        iE = irec[8];                        // q3
#pragma unroll
            for (int n = 0; n < 4; n++) {
                const u64* jrec = js_q[(jb >> 1) + 4 * n + tig];
                ulonglong2 jA = *(const ulonglong2*)&jrec[0];
                ulonglong2 jB = *(const ulonglong2*)&jrec[2];
                ulonglong2 jC = *(const ulonglong2*)&jrec[4];
                ulonglong2 jD = *(const ulonglong2*)&jrec[6];
                u64        jE = jrec[8];

                u64 gp;
                PACKW(gp, acc[n][2 * h], acc[n][2 * h + 1]);
                u64 dmu, dmu2, tt, zs, d, ds, e2;
                ADD2(dmu, iA.x, jA.x);          // mu_i + (-mu_j)
                MUL2(dmu2, dmu, dmu);
                MUL2(tt, jA.y, iB.x);           // vj * zi
                FMA2(tt, iA.y, jB.x, tt);       // + vi * zj
                ADD2(zs, iB.x, jB.x);
                FMA2(tt, dmu2, zs, tt);
                FMA2(d, tt, C13, CHALF);
                FMA2(d, gp, CM23, d);
                MUL2(ds, d, d);
                MUL2(e2, ds, CEXP2);
                float eg0, eg1;
                UNPACK2(eg0, eg1, e2);
                float w0 = ex2f(eg0), w1 = ex2f(eg1);

                u64 n1, n2, n3, d1, d2, d3, t23, e12, den, num;
                MUL2(n1, iB.y, jB.y);
                MUL2(n2, iC.x, jC.x);
                MUL2(n3, iC.y, jC.y);
                ADD2(d1, iD.x, jD.x);
                ADD2(d2, iD.y, jD.y);
                ADD2(d3, iE, jE);
                MUL2(t23, d2, d3);
                MUL2(e12, d1, d2);
                MUL2(den, e12, d3);
                MUL2(num, n1, t23);
                MUL2(t23, d1, d3);
                FMA2(num, n2, t23, num);
                FMA2(num, n3, e12, num);
                float num0, num1, den0, den1;
                UNPACK2(num0, num1, num);
                UNPACK2(den0, den1, den);
                tpart = fmaf(w0 * num0, rcpf(den0), tpart);
                tpart = fmaf(w1 * num1, rcpf(den1), tpart);
            }
        }
        if (OD[rep]) tpart += tpart;       // off-diagonal tile pairs count twice
        part += tpart;
    }

    // ---- block reduction (8 warps) ----
#pragma unroll
    for (int o = 16; o; o >>= 1) part += __shfl_xor_sync(0xffffffffu, part, o);
    if (lane == 0) red_s[warp] = part;
    __syncthreads();

    if (t == 0) {
        float s = 0.0f;
#pragma unroll
        for (int w = 0; w < 8; w++) s += red_s[w];
        g_partial[bid] = s;
        __threadfence();
        is_last = (atomicAdd(&g_count, 1) == NLAUNCH - 1);
    }
    __syncthreads();

    // ---- last block: deterministic final reduction ----
    if (is_last) {
        __shared__ double dred[8];
        double s = 0.0;
        for (int i = t; i < NLAUNCH; i += 256)
            s += (double)__ldcg(&g_partial[i]);
#pragma unroll
        for (int o = 16; o; o >>= 1)
            s += __longlong_as_double(
                 __shfl_xor_sync(0xffffffffu, __double_as_longlong(s), o));
        if (lane == 0) dred[warp] = s;
        __syncthreads();
        if (t == 0) {
            double total = 0.0;
#pragma unroll
            for (int w = 0; w < 8; w++) total += dred[w];
            double score = total / ((double)BB * PCH * NN);
            out[0] = (float)(1.0 - score / (double)NN);
            g_count = 0;                   // reset for graph replay
        }
    }
}

extern "C" void kernel_launch(void* const* d_in, const int* in_sizes, int n_in,
                              void* d_out, int out_size) {
    const float* f = (const float*)d_in[0];
    const float* p = (const float*)d_in[1];
    precompute_kernel<<<(BB * NN + 63) / 64, 64>>>(f, p);
    pair_kernel<<<NLAUNCH, 256>>>((float*)d_out);
}

// round 16
// speedup vs baseline: 1.1089x; 1.1089x over previous
#include <cuda_runtime.h>
#include <math.h>
#include <stdint.h>

#define NN      2304                    // 48*48
#define BB      2
#define CF      32
#define TILE    64
#define NT      (NN / TILE)             // 36
#define TPAIRS  (NT * (NT + 1) / 2)     // 666
#define NWORK   (BB * TPAIRS)           // 1332 tile-pairs
#define NLAUNCH 444                     // 148 SMs x 3 resident, single wave
#define NREP    3                       // every block does exactly 3 tile-pairs
#define PCH     3
#define KP      2.8853900817779268f     // 4 / ln(4)
#define CEXP    -5.770780163555851f     // -4 * log2(e)
#define SQ2     1.4142135623730951f
#define PITCH   36                      // u32 pitch, conflict-free frag loads

typedef unsigned long long u64;
typedef unsigned int u32;

// ---- scratch (no allocations allowed) ----
__device__ float4   g_st4[BB * NN];     // (mu, var, 0.25/var, -mu)
__device__ float4   g_pa4[BB * NN];     // (sqrt2*pE1..3, q1^2)
__device__ float2   g_pb2[BB * NN];     // (q2^2, q3^2)
__device__ __align__(16) u32 g_ftf[BB * NN * CF];   // normalized tf32, node-major
__device__ float    g_partial[NLAUNCH];
__device__ int      g_count = 0;

// ---- packed f32x2 helpers (sm_103a) ----
#define FMA2(d, a, b, c) asm("fma.rn.f32x2 %0, %1, %2, %3;" \
    : "=l"(d) : "l"(a), "l"(b), "l"(c))
#define MUL2(d, a, b) asm("mul.rn.f32x2 %0, %1, %2;" : "=l"(d) : "l"(a), "l"(b))
#define ADD2(d, a, b) asm("add.rn.f32x2 %0, %1, %2;" : "=l"(d) : "l"(a), "l"(b))
#define PACK2(d, x) asm("mov.b64 %0, {%1, %1};" : "=l"(d) : "f"(x))
#define PACKW(d, lo, hi) asm("mov.b64 %0, {%1, %2};" : "=l"(d) : "f"(lo), "f"(hi))
#define UNPACK2(lo, hi, v) asm("mov.b64 {%0, %1}, %2;" : "=f"(lo), "=f"(hi) : "l"(v))
#define CVT_TF32(d, x) asm("cvt.rna.tf32.f32 %0, %1;" : "=r"(d) : "f"(x))

__device__ __forceinline__ float ex2f(float x) {
    float r; asm("ex2.approx.f32 %0, %1;" : "=f"(r) : "f"(x)); return r;
}
__device__ __forceinline__ float rcpf(float x) {
    float r; asm("rcp.approx.f32 %0, %1;" : "=f"(r) : "f"(x)); return r;
}
__device__ __forceinline__ u32 smem_u32(const void* p) {
    u32 a; asm("{ .reg .u64 t; cvta.to.shared.u64 t, %1; cvt.u32.u64 %0, t; }"
               : "=r"(a) : "l"(p));
    return a;
}
#define CP_ASYNC16(daddr, gp) asm volatile( \
    "cp.async.cg.shared.global [%0], [%1], 16;" :: "r"(daddr), "l"(gp) : "memory")
#define CP_COMMIT() asm volatile("cp.async.commit_group;" ::: "memory")
#define CP_WAIT(n)  asm volatile("cp.async.wait_group %0;" :: "n"(n) : "memory")

// m16n8k8 tf32 mma, D += A*B  (row.col)
#define MMA_TF32(d, a0, a1, a2, a3, b0, b1) asm volatile( \
    "mma.sync.aligned.m16n8k8.row.col.f32.tf32.tf32.f32 " \
    "{%0,%1,%2,%3}, {%4,%5,%6,%7}, {%8,%9}, {%0,%1,%2,%3};" \
    : "+f"((d)[0]), "+f"((d)[1]), "+f"((d)[2]), "+f"((d)[3]) \
    : "r"(a0), "r"(a1), "r"(a2), "r"(a3), "r"(b0), "r"(b1))

// ============================================================
// Kernel A: stats + softmax + normalized tf32 feature rows
// ============================================================
__global__ void precompute_kernel(const float* __restrict__ f,
                                  const float* __restrict__ p) {
    int idx = blockIdx.x * 64 + threadIdx.x;
    if (idx >= BB * NN) return;
    int b = idx / NN;
    int n = idx - b * NN;

    const float* fb = f + (size_t)b * CF * NN + n;
    float v[CF];
    float s = 0.0f, ss = 0.0f;
#pragma unroll
    for (int c = 0; c < CF; c++) {
        v[c] = fb[c * NN];
        s += v[c];
        ss = fmaf(v[c], v[c], ss);
    }
    float mu  = s * (1.0f / CF);
    float var = (ss - s * mu) * (1.0f / (CF - 1));
    g_st4[idx] = make_float4(mu, var, 0.25f / var, -mu);

    float inorm = rsqrtf(ss);
    u32* frow = &g_ftf[idx * CF];
#pragma unroll
    for (int c4 = 0; c4 < CF / 4; c4++) {
        uint4 o;
        CVT_TF32(o.x, v[4 * c4 + 0] * inorm);
        CVT_TF32(o.y, v[4 * c4 + 1] * inorm);
        CVT_TF32(o.z, v[4 * c4 + 2] * inorm);
        CVT_TF32(o.w, v[4 * c4 + 3] * inorm);
        *(uint4*)&frow[4 * c4] = o;
    }

    const float* pp = p + (size_t)b * 4 * NN + n;
    float e0 = __expf(pp[0]);
    float e1 = __expf(pp[NN]);
    float e2 = __expf(pp[2 * NN]);
    float e3 = __expf(pp[3 * NN]);
    float inv = __fdividef(1.0f, e0 + e1 + e2 + e3);
    float q1 = e1 * inv, q2 = e2 * inv, q3 = e3 * inv;
    float E1 = fmaf(KP * q1, __logf(q1), 1.0f);
    float E2 = fmaf(KP * q2, __logf(q2), 1.0f);
    float E3 = fmaf(KP * q3, __logf(q3), 1.0f);
    g_pa4[idx] = make_float4(SQ2 * q1 * E1, SQ2 * q2 * E2, SQ2 * q3 * E3, q1 * q1);
    g_pb2[idx] = make_float2(q2 * q2, q3 * q3);
}

// ============================================================
// Kernel B: 444 blocks x 256 thr (occ 3, single wave, 3 reps)
//   R10 structure; stat staging split across all 256 threads
//   (2 threads per node: slots 0-4 / 5-8)
// ============================================================
__global__ void __launch_bounds__(256, 3) pair_kernel(float* __restrict__ out) {
    __shared__ __align__(16) u32 ftile[2][2][TILE][PITCH];  // [buf][side][row][k]
    __shared__ __align__(16) u64 id_q[TILE][10];            // i recs (dup pairs)
    __shared__ __align__(16) u64 js_q[TILE / 2][10];        // j recs (j, j+1)
    __shared__ float red_s[8];
    __shared__ int   is_last;

    int bid  = blockIdx.x;
    int t    = threadIdx.x;
    int lane = t & 31, warp = t >> 5;
    int g    = lane >> 2, tig = lane & 3;   // mma fragment coords
    int ar0  = (warp & 3) * 16 + g;         // first i row of this thread
    int jb   = (warp >> 2) * 32;            // warp's j block

    // decode rep -> (b, i0, j0, offdiag)
    int I0[NREP], J0[NREP], BN[NREP], OD[NREP];
#pragma unroll
    for (int rep = 0; rep < NREP; rep++) {
        int tp = bid + rep * NLAUNCH;          // unique in [0, 1332)
        int b  = tp / TPAIRS;
        int r  = tp - b * TPAIRS;
        int ti = 0;
        while (r >= NT - ti) { r -= NT - ti; ti++; }
        int tj = ti + r;
        BN[rep] = b * NN;
        I0[rep] = ti * TILE;
        J0[rep] = tj * TILE;
        OD[rep] = (ti != tj);
    }

    u64 C13, CM23, CHALF, CEXP2;
    PACK2(C13,   (1.0f / 3.0f));
    PACK2(CM23, (-2.0f / 3.0f));
    PACK2(CHALF, 0.5f);
    PACK2(CEXP2, CEXP);

    // stat staging identity: 2 threads per node, all 256 threads used
    int sside = t >> 7;                 // 0: i side, 1: j side
    int snode = (t & 127) >> 1;         // node within tile (0..63)
    int shalf = t & 1;                  // 0: slots 0-4, 1: slots 5-8

    // prologue: stage f tiles for rep 0 into buf 0
#pragma unroll
    for (int k = 0; k < 4; k++) {
        int ch   = t + 256 * k;             // 0..1023 16B chunks
        int sg   = ch & 7;
        int rw   = (ch >> 3) & 63;
        int sd   = ch >> 9;
        int base = sd ? J0[0] : I0[0];
        const u32* gp = &g_ftf[(BN[0] + base + rw) * CF + sg * 4];
        CP_ASYNC16(smem_u32(&ftile[0][sd][rw][sg * 4]), gp);
    }
    CP_COMMIT();

    float part = 0.0f;

#pragma unroll 1
    for (int rep = 0; rep < NREP; rep++) {
        int cur = rep & 1;
        int bNN = BN[rep], i0 = I0[rep], j0 = J0[rep];

        __syncthreads();                    // prev compute done; stat bufs free

        // ---- stage stat records (2 threads per node) ----
        {
            int src = bNN + (sside ? j0 : i0) + snode;
            if (sside == 0) {
                u64* dst = id_q[snode];
                if (shalf == 0) {           // slots 0-4: mu, v, z, pE1, pE2
                    float4 si = g_st4[src];
                    float4 pi = g_pa4[src];
                    float rec[5] = {si.x, si.y, si.z, pi.x, pi.y};
#pragma unroll
                    for (int a = 0; a < 5; a++) {
                        u64 dv; PACK2(dv, rec[a]);
                        dst[a] = dv;
                    }
                } else {                    // slots 5-8: pE3, q1^2, q2^2, q3^2
                    float4 pi = g_pa4[src];
                    float2 qi = g_pb2[src];
                    float rec[4] = {pi.z, pi.w, qi.x, qi.y};
#pragma unroll
                    for (int a = 0; a < 4; a++) {
                        u64 dv; PACK2(dv, rec[a]);
                        dst[5 + a] = dv;
                    }
                }
            } else {
                float* dst = (float*)js_q[snode >> 1] + (snode & 1);
                if (shalf == 0) {           // slots 0-4: -mu, v, z, pE1, pE2
                    float4 sj = g_st4[src];
                    float4 pj = g_pa4[src];
                    dst[0] = sj.w;  dst[2] = sj.y;  dst[4] = sj.z;
                    dst[6] = pj.x;  dst[8] = pj.y;
                } else {                    // slots 5-8: pE3, q1^2, q2^2, q3^2
                    float4 pj = g_pa4[src];
                    float2 qj = g_pb2[src];
                    dst[10] = pj.z;  dst[12] = pj.w;
                    dst[14] = qj.x;  dst[16] = qj.y;
                }
            }
        }

        // ---- stage f tiles for rep+1 into the other buffer ----
        if (rep + 1 < NREP) {
#pragma unroll
            for (int k = 0; k < 4; k++) {
                int ch   = t + 256 * k;
                int sg   = ch & 7;
                int rw   = (ch >> 3) & 63;
                int sd   = ch >> 9;
                int base = sd ? J0[rep + 1] : I0[rep + 1];
                const u32* gp = &g_ftf[(BN[rep + 1] + base + rw) * CF + sg * 4];
                CP_ASYNC16(smem_u32(&ftile[1 - cur][sd][rw][sg * 4]), gp);
            }
            CP_COMMIT();
            CP_WAIT(1);                     // cur's group done
        } else {
            CP_WAIT(0);
        }
        __syncthreads();                    // staging visible

        // ---- gram via mma.sync: warp tile 16i x 32j, K=32 ----
        const u32 (*as32)[PITCH] = ftile[cur][0];
        const u32 (*bs32)[PITCH] = ftile[cur][1];
        float acc[4][4];
#pragma unroll
        for (int n = 0; n < 4; n++)
#pragma unroll
            for (int c = 0; c < 4; c++) acc[n][c] = 0.0f;

#pragma unroll
        for (int kk = 0; kk < 4; kk++) {
            int kb = 8 * kk + tig;
            u32 a0 = as32[ar0][kb];
            u32 a1 = as32[ar0 + 8][kb];
            u32 a2 = as32[ar0][kb + 4];
            u32 a3 = as32[ar0 + 8][kb + 4];
#pragma unroll
            for (int n = 0; n < 4; n++) {
                int bc = jb + 8 * n + g;
                u32 b0 = bs32[bc][kb];
                u32 b1 = bs32[bc][kb + 4];
                MMA_TF32(acc[n], a0, a1, a2, a3, b0, b1);
            }
        }

        // ---- epilogue: record loads, f32x2 math ----
        float tpart = 0.0f;
#pragma unroll
        for (int h = 0; h < 2; h++) {
            const u64* irec = id_q[ar0 + 8 * h];
            ulonglong2 iA = *(const ulonglong2*)&irec[0];   // mu, v
            ulonglong2 iB = *(const ulonglong2*)&irec[2];   // z, pE1
            ulonglong2 iC = *(const ulonglong2*)&irec[4];   // pE2, pE3
            ulonglong2 iD = *(const ulonglong2*)&irec[6];   // q1, q2
            u64        iE = irec[8];                        // q3
#pragma unroll
            for (int n = 0; n < 4; n++) {
                const u64* jrec = js_q[(jb >> 1) + 4 * n + tig];
                ulonglong2 jA = *(const ulonglong2*)&jrec[0];
                ulonglong2 jB = *(const ulonglong2*)&jrec[2];
                ulonglong2 jC = *(const ulonglong2*)&jrec[4];
                ulonglong2 jD = *(const ulonglong2*)&jrec[6];
                u64        jE = jrec[8];

                u64 gp;
                PACKW(gp, acc[n][2 * h], acc[n][2 * h + 1]);
                u64 dmu, dmu2, tt, zs, d, ds, e2;
                ADD2(dmu, iA.x, jA.x);          // mu_i + (-mu_j)
                MUL2(dmu2, dmu, dmu);
                MUL2(tt, jA.y, iB.x);           // vj * zi
                FMA2(tt, iA.y, jB.x, tt);       // + vi * zj
                ADD2(zs, iB.x, jB.x);
                FMA2(tt, dmu2, zs, tt);
                FMA2(d, tt, C13, CHALF);
                FMA2(d, gp, CM23, d);
                MUL2(ds, d, d);
                MUL2(e2, ds, CEXP2);
                float eg0, eg1;
                UNPACK2(eg0, eg1, e2);
                float w0 = ex2f(eg0), w1 = ex2f(eg1);

                u64 n1, n2, n3, d1, d2, d3, t23, e12, den, num;
                MUL2(n1, iB.y, jB.y);
                MUL2(n2, iC.x, jC.x);
                MUL2(n3, iC.y, jC.y);
                ADD2(d1, iD.x, jD.x);
                ADD2(d2, iD.y, jD.y);
                ADD2(d3, iE, jE);
                MUL2(t23, d2, d3);
                MUL2(e12, d1, d2);
                MUL2(den, e12, d3);
                MUL2(num, n1, t23);
                MUL2(t23, d1, d3);
                FMA2(num, n2, t23, num);
                FMA2(num, n3, e12, num);
                float num0, num1, den0, den1;
                UNPACK2(num0, num1, num);
                UNPACK2(den0, den1, den);
                tpart = fmaf(w0 * num0, rcpf(den0), tpart);
                tpart = fmaf(w1 * num1, rcpf(den1), tpart);
            }
        }
        if (OD[rep]) tpart += tpart;       // off-diagonal tile pairs count twice
        part += tpart;
    }

    // ---- block reduction (8 warps) ----
#pragma unroll
    for (int o = 16; o; o >>= 1) part += __shfl_xor_sync(0xffffffffu, part, o);
    if (lane == 0) red_s[warp] = part;
    __syncthreads();

    if (t == 0) {
        float s = 0.0f;
#pragma unroll
        for (int w = 0; w < 8; w++) s += red_s[w];
        g_partial[bid] = s;
        __threadfence();
        is_last = (atomicAdd(&g_count, 1) == NLAUNCH - 1);
    }
    __syncthreads();

    // ---- last block: deterministic final reduction ----
    if (is_last) {
        __shared__ double dred[8];
        double s = 0.0;
        for (int i = t; i < NLAUNCH; i += 256)
            s += (double)__ldcg(&g_partial[i]);
#pragma unroll
        for (int o = 16; o; o >>= 1)
            s += __longlong_as_double(
                 __shfl_xor_sync(0xffffffffu, __double_as_longlong(s), o));
        if (lane == 0) dred[warp] = s;
        __syncthreads();
        if (t == 0) {
            double total = 0.0;
#pragma unroll
            for (int w = 0; w < 8; w++) total += dred[w];
            double score = total / ((double)BB * PCH * NN);
            out[0] = (float)(1.0 - score / (double)NN);
            g_count = 0;                   // reset for graph replay
        }
    }
}

extern "C" void kernel_launch(void* const* d_in, const int* in_sizes, int n_in,
                              void* d_out, int out_size) {
    const float* f = (const float*)d_in[0];
    const float* p = (const float*)d_in[1];
    precompute_kernel<<<(BB * NN + 63) / 64, 64>>>(f, p);
    pair_kernel<<<NLAUNCH, 256>>>((float*)d_out);
}

// round 17
// speedup vs baseline: 1.2896x; 1.1629x over previous
#include <cuda_runtime.h>
#include <math.h>
#include <stdint.h>

#define NN      2304                    // 48*48
#define BB      2
#define CF      32
#define TILE    64
#define NT      (NN / TILE)             // 36
#define TPAIRS  (NT * (NT + 1) / 2)     // 666
#define NWORK   (BB * TPAIRS)           // 1332 tile-pairs
#define NLAUNCH 444                     // 148 SMs x 3 resident, single wave
#define NREP    3                       // every block does exactly 3 tile-pairs
#define PCH     3
#define KP      2.8853900817779268f     // 4 / ln(4)
#define CEXP    -5.770780163555851f     // -4 * log2(e)
#define SQ2     1.4142135623730951f
#define PITCH   36                      // u32 pitch, conflict-free frag loads

typedef unsigned long long u64;
typedef unsigned int u32;

// ---- scratch (no allocations allowed) ----
__device__ float4   g_st4[BB * NN];     // (mu, var, 0.25/var, -mu)
__device__ float4   g_pa4[BB * NN];     // (sqrt2*pE1..3, q1^2)
__device__ float2   g_pb2[BB * NN];     // (q2^2, q3^2)
__device__ __align__(16) u32 g_ftf[BB * NN * CF];   // normalized tf32, node-major
__device__ float    g_partial[NLAUNCH];
__device__ int      g_count = 0;

// ---- packed f32x2 helpers (sm_103a) ----
#define FMA2(d, a, b, c) asm("fma.rn.f32x2 %0, %1, %2, %3;" \
    : "=l"(d) : "l"(a), "l"(b), "l"(c))
#define MUL2(d, a, b) asm("mul.rn.f32x2 %0, %1, %2;" : "=l"(d) : "l"(a), "l"(b))
#define ADD2(d, a, b) asm("add.rn.f32x2 %0, %1, %2;" : "=l"(d) : "l"(a), "l"(b))
#define PACK2(d, x) asm("mov.b64 %0, {%1, %1};" : "=l"(d) : "f"(x))
#define PACKW(d, lo, hi) asm("mov.b64 %0, {%1, %2};" : "=l"(d) : "f"(lo), "f"(hi))
#define UNPACK2(lo, hi, v) asm("mov.b64 {%0, %1}, %2;" : "=f"(lo), "=f"(hi) : "l"(v))
#define CVT_TF32(d, x) asm("cvt.rna.tf32.f32 %0, %1;" : "=r"(d) : "f"(x))

__device__ __forceinline__ float ex2f(float x) {
    float r; asm("ex2.approx.f32 %0, %1;" : "=f"(r) : "f"(x)); return r;
}
__device__ __forceinline__ float rcpf(float x) {
    float r; asm("rcp.approx.f32 %0, %1;" : "=f"(r) : "f"(x)); return r;
}
__device__ __forceinline__ u32 smem_u32(const void* p) {
    u32 a; asm("{ .reg .u64 t; cvta.to.shared.u64 t, %1; cvt.u32.u64 %0, t; }"
               : "=r"(a) : "l"(p));
    return a;
}
#define CP_ASYNC16(daddr, gp) asm volatile( \
    "cp.async.cg.shared.global [%0], [%1], 16;" :: "r"(daddr), "l"(gp) : "memory")
#define CP_COMMIT() asm volatile("cp.async.commit_group;" ::: "memory")
#define CP_WAIT(n)  asm volatile("cp.async.wait_group %0;" :: "n"(n) : "memory")

// m16n8k8 tf32 mma, D += A*B  (row.col)
#define MMA_TF32(d, a0, a1, a2, a3, b0, b1) asm volatile( \
    "mma.sync.aligned.m16n8k8.row.col.f32.tf32.tf32.f32 " \
    "{%0,%1,%2,%3}, {%4,%5,%6,%7}, {%8,%9}, {%0,%1,%2,%3};" \
    : "+f"((d)[0]), "+f"((d)[1]), "+f"((d)[2]), "+f"((d)[3]) \
    : "r"(a0), "r"(a1), "r"(a2), "r"(a3), "r"(b0), "r"(b1))

// ============================================================
// Kernel A: stats + softmax + normalized tf32 feature rows
// ============================================================
__global__ void precompute_kernel(const float* __restrict__ f,
                                  const float* __restrict__ p) {
    int idx = blockIdx.x * 64 + threadIdx.x;
    if (idx >= BB * NN) return;
    int b = idx / NN;
    int n = idx - b * NN;

    const float* fb = f + (size_t)b * CF * NN + n;
    float v[CF];
    float s = 0.0f, ss = 0.0f;
#pragma unroll
    for (int c = 0; c < CF; c++) {
        v[c] = fb[c * NN];
        s += v[c];
        ss = fmaf(v[c], v[c], ss);
    }
    float mu  = s * (1.0f / CF);
    float var = (ss - s * mu) * (1.0f / (CF - 1));
    g_st4[idx] = make_float4(mu, var, 0.25f / var, -mu);

    float inorm = rsqrtf(ss);
    u32* frow = &g_ftf[idx * CF];
#pragma unroll
    for (int c4 = 0; c4 < CF / 4; c4++) {
        uint4 o;
        CVT_TF32(o.x, v[4 * c4 + 0] * inorm);
        CVT_TF32(o.y, v[4 * c4 + 1] * inorm);
        CVT_TF32(o.z, v[4 * c4 + 2] * inorm);
        CVT_TF32(o.w, v[4 * c4 + 3] * inorm);
        *(uint4*)&frow[4 * c4] = o;
    }

    const float* pp = p + (size_t)b * 4 * NN + n;
    float e0 = __expf(pp[0]);
    float e1 = __expf(pp[NN]);
    float e2 = __expf(pp[2 * NN]);
    float e3 = __expf(pp[3 * NN]);
    float inv = __fdividef(1.0f, e0 + e1 + e2 + e3);
    float q1 = e1 * inv, q2 = e2 * inv, q3 = e3 * inv;
    float E1 = fmaf(KP * q1, __logf(q1), 1.0f);
    float E2 = fmaf(KP * q2, __logf(q2), 1.0f);
    float E3 = fmaf(KP * q3, __logf(q3), 1.0f);
    g_pa4[idx] = make_float4(SQ2 * q1 * E1, SQ2 * q2 * E2, SQ2 * q3 * E3, q1 * q1);
    g_pb2[idx] = make_float2(q2 * q2, q3 * q3);
}

// ============================================================
// Kernel B: 444 blocks x 256 thr (occ 3, single wave, 3 reps)
//   cp.async double-buffered tf32 tiles, mma.sync gram,
//   record-packed f32x2 epilogue
// ============================================================
__global__ void __launch_bounds__(256, 3) pair_kernel(float* __restrict__ out) {
    __shared__ __align__(16) u32 ftile[2][2][TILE][PITCH];  // [buf][side][row][k]
    __shared__ __align__(16) u64 id_q[TILE][10];            // i recs (dup pairs)
    __shared__ __align__(16) u64 js_q[TILE / 2][10];        // j recs (j, j+1)
    __shared__ float red_s[8];
    __shared__ int   is_last;

    int bid  = blockIdx.x;
    int t    = threadIdx.x;
    int lane = t & 31, warp = t >> 5;
    int g    = lane >> 2, tig = lane & 3;   // mma fragment coords
    int ar0  = (warp & 3) * 16 + g;         // first i row of this thread
    int jb   = (warp >> 2) * 32;            // warp's j block

    // decode rep -> (b, i0, j0, offdiag)
    int I0[NREP], J0[NREP], BN[NREP], OD[NREP];
#pragma unroll
    for (int rep = 0; rep < NREP; rep++) {
        int tp = bid + rep * NLAUNCH;
        int b  = tp / TPAIRS;
        int r  = tp - b * TPAIRS;
        int ti = 0;
        while (r >= NT - ti) { r -= NT - ti; ti++; }
        int tj = ti + r;
        BN[rep] = b * NN;
        I0[rep] = ti * TILE;
        J0[rep] = tj * TILE;
        OD[rep] = (ti != tj);
    }

    u64 C13, CM23, CHALF, CEXP2;
    PACK2(C13,   (1.0f / 3.0f));
    PACK2(CM23, (-2.0f / 3.0f));
    PACK2(CHALF, 0.5f);
    PACK2(CEXP2, CEXP);

    // prologue: stage f tiles for rep 0 into buf 0
#pragma unroll
    for (int k = 0; k < 4; k++) {
        int ch   = t + 256 * k;             // 0..1023 16B chunks
        int sg   = ch & 7;
        int rw   = (ch >> 3) & 63;
        int sd   = ch >> 9;
        int base = sd ? J0[0] : I0[0];
        const u32* gp = &g_ftf[(BN[0] + base + rw) * CF + sg * 4];
        CP_ASYNC16(smem_u32(&ftile[0][sd][rw][sg * 4]), gp);
    }
    CP_COMMIT();

    float part = 0.0f;

#pragma unroll 1
    for (int rep = 0; rep < NREP; rep++) {
        int cur = rep & 1;
        int bNN = BN[rep], i0 = I0[rep], j0 = J0[rep];

        __syncthreads();                    // prev compute done; stat bufs free

        // ---- stage stat records ----
        if (t < TILE) {
            int e = t;
            float4 si = g_st4[bNN + i0 + e];
            float4 pi = g_pa4[bNN + i0 + e];
            float2 qi = g_pb2[bNN + i0 + e];
            float rec[9] = {si.x, si.y, si.z, pi.x, pi.y, pi.z, pi.w, qi.x, qi.y};
            u64* dst = id_q[e];
#pragma unroll
            for (int a = 0; a < 9; a++) {
                u64 dv; PACK2(dv, rec[a]);
                dst[a] = dv;
            }
        } else if (t < 2 * TILE) {
            int e = t - TILE;
            float4 sj = g_st4[bNN + j0 + e];
            float4 pj = g_pa4[bNN + j0 + e];
            float2 qj = g_pb2[bNN + j0 + e];
            float rec[9] = {sj.w, sj.y, sj.z, pj.x, pj.y, pj.z, pj.w, qj.x, qj.y};
            float* dst = (float*)js_q[e >> 1] + (e & 1);
#pragma unroll
            for (int a = 0; a < 9; a++) dst[2 * a] = rec[a];
        }

        // ---- stage f tiles for rep+1 into the other buffer ----
        if (rep + 1 < NREP) {
#pragma unroll
            for (int k = 0; k < 4; k++) {
                int ch   = t + 256 * k;
                int sg   = ch & 7;
                int rw   = (ch >> 3) & 63;
                int sd   = ch >> 9;
                int base = sd ? J0[rep + 1] : I0[rep + 1];
                const u32* gp = &g_ftf[(BN[rep + 1] + base + rw) * CF + sg * 4];
                CP_ASYNC16(smem_u32(&ftile[1 - cur][sd][rw][sg * 4]), gp);
            }
            CP_COMMIT();
            CP_WAIT(1);                     // cur's group done
        } else {
            CP_WAIT(0);
        }
        __syncthreads();                    // staging visible

        // ---- gram via mma.sync: warp tile 16i x 32j, K=32 ----
        const u32 (*as32)[PITCH] = ftile[cur][0];
        const u32 (*bs32)[PITCH] = ftile[cur][1];
        float acc[4][4];
#pragma unroll
        for (int n = 0; n < 4; n++)
#pragma unroll
            for (int c = 0; c < 4; c++) acc[n][c] = 0.0f;

#pragma unroll
        for (int kk = 0; kk < 4; kk++) {
            int kb = 8 * kk + tig;
            u32 a0 = as32[ar0][kb];
            u32 a1 = as32[ar0 + 8][kb];
            u32 a2 = as32[ar0][kb + 4];
            u32 a3 = as32[ar0 + 8][kb + 4];
#pragma unroll
            for (int n = 0; n < 4; n++) {
                int bc = jb + 8 * n + g;
                u32 b0 = bs32[bc][kb];
                u32 b1 = bs32[bc][kb + 4];
                MMA_TF32(acc[n], a0, a1, a2, a3, b0, b1);
            }
        }

        // ---- epilogue: record loads, f32x2 math ----
        float tpart = 0.0f;
#pragma unroll
        for (int h = 0; h < 2; h++) {
            const u64* irec = id_q[ar0 + 8 * h];
            ulonglong2 iA = *(const ulonglong2*)&irec[0];   // mu, v
            ulonglong2 iB = *(const ulonglong2*)&irec[2];   // z, pE1
            ulonglong2 iC = *(const ulonglong2*)&irec[4];   // pE2, pE3
            ulonglong2 iD = *(const ulonglong2*)&irec[6];   // q1, q2
            u64        iE = irec[8];                        // q3
#pragma unroll
            for (int n = 0; n < 4; n++) {
                const u64* jrec = js_q[(jb >> 1) + 4 * n + tig];
                ulonglong2 jA = *(const ulonglong2*)&jrec[0];
                ulonglong2 jB = *(const ulonglong2*)&jrec[2];
                ulonglong2 jC = *(const ulonglong2*)&jrec[4];
                ulonglong2 jD = *(const ulonglong2*)&jrec[6];
                u64        jE = jrec[8];

                u64 gp;
                PACKW(gp, acc[n][2 * h], acc[n][2 * h + 1]);
                u64 dmu, dmu2, tt, zs, d, ds, e2;
                ADD2(dmu, iA.x, jA.x);          // mu_i + (-mu_j)
                MUL2(dmu2, dmu, dmu);
                MUL2(tt, jA.y, iB.x);           // vj * zi
                FMA2(tt, iA.y, jB.x, tt);       // + vi * zj
                ADD2(zs, iB.x, jB.x);
                FMA2(tt, dmu2, zs, tt);
                FMA2(d, tt, C13, CHALF);
                FMA2(d, gp, CM23, d);
                MUL2(ds, d, d);
                MUL2(e2, ds, CEXP2);
                float eg0, eg1;
                UNPACK2(eg0, eg1, e2);
                float w0 = ex2f(eg0), w1 = ex2f(eg1);

                u64 n1, n2, n3, d1, d2, d3, t23, e12, den, num;
                MUL2(n1, iB.y, jB.y);
                MUL2(n2, iC.x, jC.x);
                MUL2(n3, iC.y, jC.y);
                ADD2(d1, iD.x, jD.x);
                ADD2(d2, iD.y, jD.y);
                ADD2(d3, iE, jE);
                MUL2(t23, d2, d3);
                MUL2(e12, d1, d2);
                MUL2(den, e12, d3);
                MUL2(num, n1, t23);
                MUL2(t23, d1, d3);
                FMA2(num, n2, t23, num);
                FMA2(num, n3, e12, num);
                float num0, num1, den0, den1;
                UNPACK2(num0, num1, num);
                UNPACK2(den0, den1, den);
                tpart = fmaf(w0 * num0, rcpf(den0), tpart);
                tpart = fmaf(w1 * num1, rcpf(den1), tpart);
            }
        }
        if (OD[rep]) tpart += tpart;       // off-diagonal tile pairs count twice
        part += tpart;
    }

    // ---- block reduction (8 warps) ----
#pragma unroll
    for (int o = 16; o; o >>= 1) part += __shfl_xor_sync(0xffffffffu, part, o);
    if (lane == 0) red_s[warp] = part;
    __syncthreads();

    if (t == 0) {
        float s = 0.0f;
#pragma unroll
        for (int w = 0; w < 8; w++) s += red_s[w];
        g_partial[bid] = s;
        __threadfence();
        is_last = (atomicAdd(&g_count, 1) == NLAUNCH - 1);
    }
    __syncthreads();

    // ---- last block: deterministic final reduction ----
    if (is_last) {
        __shared__ double dred[8];
        double s = 0.0;
        for (int i = t; i < NLAUNCH; i += 256)
            s += (double)__ldcg(&g_partial[i]);
#pragma unroll
        for (int o = 16; o; o >>= 1)
            s += __longlong_as_double(
                 __shfl_xor_sync(0xffffffffu, __double_as_longlong(s), o));
        if (lane == 0) dred[warp] = s;
        __syncthreads();
        if (t == 0) {
            double total = 0.0;
#pragma unroll
            for (int w = 0; w < 8; w++) total += dred[w];
            double score = total / ((double)BB * PCH * NN);
            out[0] = (float)(1.0 - score / (double)NN);
            g_count = 0;                   // reset for graph replay
        }
    }
}

extern "C" void kernel_launch(void* const* d_in, const int* in_sizes, int n_in,
                              void* d_out, int out_size) {
    const float* f = (const float*)d_in[0];
    const float* p = (const float*)d_in[1];
    precompute_kernel<<<(BB * NN + 63) / 64, 64>>>(f, p);
    pair_kernel<<<NLAUNCH, 256>>>((float*)d_out);
}